// round 1
// baseline (speedup 1.0000x reference)
#include <cuda_runtime.h>
#include <math.h>

#define KGRID 64
#define NRAY2 4096
#define NS    64
#define OUTN  192
#define OUT3  (OUTN*OUTN*OUTN)

// ---------------- scratch (device globals; no allocation allowed) ----------------
__device__ float gMX[NRAY2 * NS];   // (ray, sample) = (i*64+j, s) -> X path *2-1
__device__ float gMY[NRAY2 * NS];
__device__ float gMZ[NRAY2 * NS];
__device__ float gMC[12];           // M_CRD rows 0..3, cols 0..2 (float32 of f64 build)
__device__ float gMD[12];           // M_DRV rows 0..3, cols 0..2

// ---------------- matrix construction (double, matches numpy f64 -> f32) ----------------
__device__ __forceinline__ void mm4(const double* A, const double* B, double* C) {
    for (int i = 0; i < 4; i++)
        for (int j = 0; j < 4; j++) {
            double s = 0.0;
            for (int k = 0; k < 4; k++) s += A[i*4+k] * B[k*4+j];
            C[i*4+j] = s;
        }
}
__device__ __forceinline__ void m_ry(double t, double* M) {
    double c = cos(t), s = sin(t);
    double v[16] = {1,0,0,0, 0,c,-s,0, 0,s,c,0, 0,0,0,1};
    for (int i = 0; i < 16; i++) M[i] = v[i];
}
__device__ __forceinline__ void m_rx(double t, double* M) {
    double c = cos(t), s = sin(t);
    double v[16] = {c,0,-s,0, 0,1,0,0, s,0,c,0, 0,0,0,1};
    for (int i = 0; i < 16; i++) M[i] = v[i];
}
__device__ __forceinline__ void m_rz(double t, double* M) {
    double c = cos(t), s = sin(t);
    double v[16] = {c,-s,0,0, s,c,0,0, 0,0,1,0, 0,0,0,1};
    for (int i = 0; i < 16; i++) M[i] = v[i];
}

__global__ void init_mats_kernel() {
    if (threadIdx.x != 0) return;
    const double TX = 0.1, TY = 0.05, TZ = 0.02, CX = 0.5;
    double RY[16], RX[16], RZ[16], RX_[16], RY_[16], RZ_[16];
    m_ry(-TY, RY);  m_ry( TY, RY_);
    m_rx( TX, RX);  m_rx(-TX, RX_);
    m_rz(-TZ, RZ);  m_rz( TZ, RZ_);
    double S1[16] = {1,0,0,0, 0,1,0,0, 0,0,1,0, -CX,-CX,-CX,1};
    double S2[16] = {1,0,0,0, 0,1,0,0, 0,0,1,0,  CX, CX, CX,1};
    double T1[16], T2[16], T3[16], T4[16];
    mm4(S1, RZ, T1); mm4(T1, RY, T2); mm4(T2, RX, T3); mm4(T3, S2, T4);  // M_CRD
    for (int i = 0; i < 4; i++)
        for (int j = 0; j < 3; j++) gMC[i*3+j] = (float)T4[i*4+j];
    mm4(RX_, RY_, T1); mm4(T1, RZ_, T2);                                  // M_DRV
    for (int i = 0; i < 4; i++)
        for (int j = 0; j < 3; j++) gMD[i*3+j] = (float)T2[i*4+j];
}

// ---------------- phase 1: ray tracing, one warp per ray, lanes 0..26 = neighbors ----------------
__global__ void __launch_bounds__(256) ray_kernel(const float* __restrict__ RI,
                                                  const float* __restrict__ ray0) {
    int gtid = blockIdx.x * blockDim.x + threadIdx.x;
    int ray  = gtid >> 5;
    int lane = gtid & 31;
    if (ray >= NRAY2) return;

    float mc[12], md[12];
#pragma unroll
    for (int i = 0; i < 12; i++) { mc[i] = gMC[i]; md[i] = gMD[i]; }

    const float* r0 = ray0 + ray * 5;
    float X = r0[0], dX1 = r0[1], Y = r0[2], dY1 = r0[3], z = r0[4];

    // neighbor offsets: m = i*9 + j*3 + k; XR=_r[j], YR=_r[i], ZR=_r[k], _r={-1,0,1}
    float xr = (float)((lane / 3) % 3 - 1);
    float yr = (float)(lane / 9 - 1);
    float zr = (float)(lane % 3 - 1);
    bool  act = (lane < 27);

    const float2* ri2 = (const float2*)RI;
    const float STEP = 1.0f / 63.0f;

    if (lane == 0) {
        gMX[ray * NS] = 2.0f * X - 1.0f;
        gMY[ray * NS] = 2.0f * Y - 1.0f;
        gMZ[ray * NS] = 2.0f * z - 1.0f;
    }

    for (int s = 1; s < NS; s++) {
        // t = [Y, X, z, 1] @ M_CRD ; x=t1, y=t0, z'=t2
        float t0 = Y * mc[0] + X * mc[3] + z * mc[6] + mc[9];
        float t1 = Y * mc[1] + X * mc[4] + z * mc[7] + mc[10];
        float t2 = Y * mc[2] + X * mc[5] + z * mc[8] + mc[11];
        float Xv = t1, Yv = t0, Zv = t2;

        float s_norm = 0.f, s_nus = 0.f, s_nx = 0.f, s_ny = 0.f,
              s_nz = 0.f, s_ndx = 0.f, s_ndy = 0.f, s_ndz = 0.f;
        if (act) {
            float fXn = fminf(fmaxf(rintf(Xv * 64.0f) + xr, 0.0f), 63.0f);
            float fYn = fminf(fmaxf(rintf(Yv * 64.0f) + yr, 0.0f), 63.0f);
            float fZn = fminf(fmaxf(rintf(Zv * 64.0f) + zr, 0.0f), 63.0f);
            int iX = (int)fXn, iY = (int)fYn, iZ = (int)fZn;
            int lin = (iY << 12) + (iX << 6) + iZ;
            float2 ri = __ldg(&ri2[lin]);
            float dx = fXn / 63.0f - Xv;
            float dy = fYn / 63.0f - Yv;
            float dzv = fZn / 63.0f - Zv;
            float A = ri.x, sg = ri.y;
            float inv_s2 = 1.0f / (sg * sg);
            float r2 = dx * dx + dy * dy + dzv * dzv;
            float ni = expf(-r2 * 0.5f * inv_s2) + 2e-7f;
            float nu = ni * A;
            float hx = dx * inv_s2, hy = dy * inv_s2, hz = dzv * inv_s2;
            s_norm = ni;       s_nus = nu;
            s_nx = nu * hx;    s_ny = nu * hy;    s_nz = nu * hz;
            s_ndx = ni * hx;   s_ndy = ni * hy;   s_ndz = ni * hz;
        }
#pragma unroll
        for (int off = 16; off > 0; off >>= 1) {
            s_norm += __shfl_xor_sync(0xffffffffu, s_norm, off);
            s_nus  += __shfl_xor_sync(0xffffffffu, s_nus,  off);
            s_nx   += __shfl_xor_sync(0xffffffffu, s_nx,   off);
            s_ny   += __shfl_xor_sync(0xffffffffu, s_ny,   off);
            s_nz   += __shfl_xor_sync(0xffffffffu, s_nz,   off);
            s_ndx  += __shfl_xor_sync(0xffffffffu, s_ndx,  off);
            s_ndy  += __shfl_xor_sync(0xffffffffu, s_ndy,  off);
            s_ndz  += __shfl_xor_sync(0xffffffffu, s_ndz,  off);
        }
        float n = s_nus / s_norm;
        float inv_n2 = 1.0f / (s_norm * s_norm);
        float nx = (s_norm * s_nx - s_nus * s_ndx) * inv_n2;
        float ny = (s_norm * s_ny - s_nus * s_ndy) * inv_n2;
        float nz = (s_norm * s_nz - s_nus * s_ndz) * inv_n2;

        // d = [ny, nx, nz, 1] @ M_DRV ; dndx=d1, dndz=d2, dndy=d0
        float d0 = ny * md[0] + nx * md[3] + nz * md[6] + md[9];
        float d1 = ny * md[1] + nx * md[4] + nz * md[7] + md[10];
        float d2 = ny * md[2] + nx * md[5] + nz * md[8] + md[11];
        float dndx = d1, dndz = d2, dndy = d0;

        float dX2 = (dndx - dndz * dX1) * (1.0f + dX1 * dX1) / n;
        float dY2 = (dndy - dndz * dY1) * (1.0f + dY1 * dY1) / n;

        X += dX1 * STEP; dX1 += dX2 * STEP;
        Y += dY1 * STEP; dY1 += dY2 * STEP;
        z += STEP;

        if (lane == 0) {
            gMX[ray * NS + s] = 2.0f * X - 1.0f;
            gMY[ray * NS + s] = 2.0f * Y - 1.0f;
            gMZ[ray * NS + s] = 2.0f * z - 1.0f;
        }
    }
}

// ---------------- phase 2: fused trilinear resize (64^3 -> 192^3) + grid_sample ----------------
__device__ __forceinline__ float tri_interp(const float* __restrict__ m, int base,
                                            float wi, float wj, float ws) {
    float u = 1.0f - wi, v = 1.0f - wj, w = 1.0f - ws;
    float g00 = m[base]        * u + m[base + 4096]      * wi;   // (i lerp) j0,s0
    float g10 = m[base + 64]   * u + m[base + 4160]      * wi;   // j1,s0
    float g01 = m[base + 1]    * u + m[base + 4097]      * wi;   // j0,s1
    float g11 = m[base + 65]   * u + m[base + 4161]      * wi;   // j1,s1
    float h0  = g00 * v + g10 * wj;
    float h1  = g01 * v + g11 * wj;
    return h0 * w + h1 * ws;
}

__global__ void __launch_bounds__(256) sample_kernel(const float* __restrict__ vol,
                                                     float* __restrict__ out) {
    int idx = blockIdx.x * blockDim.x + threadIdx.x;
    if (idx >= OUT3) return;
    int cc = idx % OUTN;
    int bb = (idx / OUTN) % OUTN;
    int aa = idx / (OUTN * OUTN);

    const float scale = 63.0f / 191.0f;   // linspace(0,63,192) step, f32 like jnp.linspace
    float pa = (float)aa * scale; int i0 = min((int)pa, 62); float wi = pa - (float)i0;
    float pb = (float)bb * scale; int j0 = min((int)pb, 62); float wj = pb - (float)j0;
    float pc = (float)cc * scale; int s0 = min((int)pc, 62); float ws = pc - (float)s0;
    int base = (i0 << 12) + (j0 << 6) + s0;

    float gx = tri_interp(gMX, base, wi, wj, ws);
    float gy = tri_interp(gMY, base, wi, wj, ws);
    float gz = tri_interp(gMZ, base, wi, wj, ws);

    float ix = (gx + 1.0f) * 0.5f * 191.0f;
    float iy = (gy + 1.0f) * 0.5f * 191.0f;
    float iz = (gz + 1.0f) * 0.5f * 191.0f;
    float x0 = floorf(ix), y0 = floorf(iy), z0 = floorf(iz);
    float fx = ix - x0, fy = iy - y0, fz = iz - z0;

    float res = 0.0f;
#pragma unroll
    for (int dz = 0; dz < 2; dz++)
#pragma unroll
        for (int dy = 0; dy < 2; dy++)
#pragma unroll
            for (int dx = 0; dx < 2; dx++) {
                float xi = x0 + (float)dx, yi = y0 + (float)dy, zi = z0 + (float)dz;
                bool inb = (xi >= 0.0f) && (xi <= 191.0f) &&
                           (yi >= 0.0f) && (yi <= 191.0f) &&
                           (zi >= 0.0f) && (zi <= 191.0f);
                float wgt = (dx ? fx : 1.0f - fx) * (dy ? fy : 1.0f - fy) * (dz ? fz : 1.0f - fz);
                int xc = (int)fminf(fmaxf(xi, 0.0f), 191.0f);
                int yc = (int)fminf(fmaxf(yi, 0.0f), 191.0f);
                int zc = (int)fminf(fmaxf(zi, 0.0f), 191.0f);
                if (inb) res += wgt * __ldg(&vol[(zc * OUTN + yc) * OUTN + xc]);
            }
    out[idx] = res;
}

// ---------------- launch ----------------
extern "C" void kernel_launch(void* const* d_in, const int* in_sizes, int n_in,
                              void* d_out, int out_size) {
    const float* phantom = nullptr;
    const float* RI      = nullptr;
    const float* ray0    = nullptr;
    for (int i = 0; i < n_in; i++) {
        if      (in_sizes[i] == OUT3)          phantom = (const float*)d_in[i];
        else if (in_sizes[i] == KGRID*KGRID*KGRID*2) RI = (const float*)d_in[i];
        else if (in_sizes[i] == NRAY2 * 5)     ray0    = (const float*)d_in[i];
    }
    float* out = (float*)d_out;

    init_mats_kernel<<<1, 32>>>();
    ray_kernel<<<(NRAY2 * 32) / 256, 256>>>(RI, ray0);
    sample_kernel<<<(OUT3 + 255) / 256, 256>>>(phantom, out);
}

// round 2
// speedup vs baseline: 1.0486x; 1.0486x over previous
#include <cuda_runtime.h>
#include <math.h>

#define KGRID 64
#define NRAY2 4096
#define NS    64
#define OUTN  192
#define OUT3  (OUTN*OUTN*OUTN)

// ---------------- scratch (device globals; no allocation allowed) ----------------
__device__ float gMX[NRAY2 * NS];
__device__ float gMY[NRAY2 * NS];
__device__ float gMZ[NRAY2 * NS];

// ---------------- compile-time matrix construction ----------------
// Taylor series sin/cos in constexpr double; |x| <= 0.1 so the series is
// converged far below double ulp (x^13/13! ~ 1.6e-23). Matches numpy f64
// within <=1 ulp, which is ~1e-16 relative on the matrix entries.
constexpr double c_sin(double x) {
    double x2 = x * x;
    return x * (1.0 + x2 * (-1.0/6.0 + x2 * (1.0/120.0 + x2 * (-1.0/5040.0
             + x2 * (1.0/362880.0 + x2 * (-1.0/39916800.0))))));
}
constexpr double c_cos(double x) {
    double x2 = x * x;
    return 1.0 + x2 * (-0.5 + x2 * (1.0/24.0 + x2 * (-1.0/720.0
             + x2 * (1.0/40320.0 + x2 * (-1.0/3628800.0 + x2 * (1.0/479001600.0))))));
}
struct M4 { double a[16]; };
constexpr M4 c_mul(const M4& A, const M4& B) {
    M4 C{};
    for (int i = 0; i < 4; i++)
        for (int j = 0; j < 4; j++) {
            double s = 0.0;
            for (int k = 0; k < 4; k++) s += A.a[i*4+k] * B.a[k*4+j];
            C.a[i*4+j] = s;
        }
    return C;
}
constexpr M4 c_ry(double t) {
    double c = c_cos(t), s = c_sin(t);
    return M4{{1,0,0,0, 0,c,-s,0, 0,s,c,0, 0,0,0,1}};
}
constexpr M4 c_rx(double t) {
    double c = c_cos(t), s = c_sin(t);
    return M4{{c,0,-s,0, 0,1,0,0, s,0,c,0, 0,0,0,1}};
}
constexpr M4 c_rz(double t) {
    double c = c_cos(t), s = c_sin(t);
    return M4{{c,-s,0,0, s,c,0,0, 0,0,1,0, 0,0,0,1}};
}
struct Mats { float mc[12]; float md[12]; };
constexpr Mats build_mats() {
    const double TX = 0.1, TY = 0.05, TZ = 0.02, CX = 0.5;
    M4 RY  = c_ry(-TY), RY_ = c_ry( TY);
    M4 RX  = c_rx( TX), RX_ = c_rx(-TX);
    M4 RZ  = c_rz(-TZ), RZ_ = c_rz( TZ);
    M4 S1{{1,0,0,0, 0,1,0,0, 0,0,1,0, -CX,-CX,-CX,1}};
    M4 S2{{1,0,0,0, 0,1,0,0, 0,0,1,0,  CX, CX, CX,1}};
    M4 M_crd = c_mul(c_mul(c_mul(c_mul(S1, RZ), RY), RX), S2);
    M4 M_drv = c_mul(c_mul(RX_, RY_), RZ_);
    Mats r{};
    for (int i = 0; i < 4; i++)
        for (int j = 0; j < 3; j++) {
            r.mc[i*3+j] = (float)M_crd.a[i*4+j];
            r.md[i*3+j] = (float)M_drv.a[i*4+j];
        }
    return r;
}
__constant__ Mats cMat = build_mats();

// ---------------- phase 1: ray tracing ----------------
// One warp per ray, lanes 0..26 = Gaussian neighbors. The RI gather for the
// NEXT step is issued before the current step's reduce chain: next position
// X+dX1*STEP depends only on current state, not on the Gaussian evaluation,
// so the ~250-cycle L2 latency overlaps the exp+shfl chain.
__global__ void __launch_bounds__(256) ray_kernel(const float* __restrict__ RI,
                                                  const float* __restrict__ ray0) {
    int gtid = blockIdx.x * blockDim.x + threadIdx.x;
    int ray  = gtid >> 5;
    int lane = gtid & 31;
    if (ray >= NRAY2) return;

    float mc[12], md[12];
#pragma unroll
    for (int i = 0; i < 12; i++) { mc[i] = cMat.mc[i]; md[i] = cMat.md[i]; }

    const float* r0 = ray0 + ray * 5;
    float X = r0[0], dX1 = r0[1], Y = r0[2], dY1 = r0[3], z = r0[4];

    float xr = (float)((lane / 3) % 3 - 1);
    float yr = (float)(lane / 9 - 1);
    float zr = (float)(lane % 3 - 1);
    bool  act = (lane < 27);

    const float2* ri2 = (const float2*)RI;
    const float STEP = 1.0f / 63.0f;

    if (lane == 0) {
        gMX[ray * NS] = 2.0f * X - 1.0f;
        gMY[ray * NS] = 2.0f * Y - 1.0f;
        gMZ[ray * NS] = 2.0f * z - 1.0f;
    }

    // Prologue: transform + gather for state 0
    float cXv, cYv, cZv, cfX, cfY, cfZ;   // carried transformed pos + neighbor coords
    float2 ri_cur = make_float2(0.f, 1.f);
    {
        float t0 = Y * mc[0] + X * mc[3] + z * mc[6] + mc[9];
        float t1 = Y * mc[1] + X * mc[4] + z * mc[7] + mc[10];
        float t2 = Y * mc[2] + X * mc[5] + z * mc[8] + mc[11];
        cXv = t1; cYv = t0; cZv = t2;
        cfX = fminf(fmaxf(rintf(cXv * 64.0f) + xr, 0.0f), 63.0f);
        cfY = fminf(fmaxf(rintf(cYv * 64.0f) + yr, 0.0f), 63.0f);
        cfZ = fminf(fmaxf(rintf(cZv * 64.0f) + zr, 0.0f), 63.0f);
        if (act) {
            int lin = ((int)cfY << 12) + ((int)cfX << 6) + (int)cfZ;
            ri_cur = __ldg(&ri2[lin]);
        }
    }

    for (int s = 1; s < NS; s++) {
        // --- next-state position (cheap; depends only on current state) ---
        float Xn = X + dX1 * STEP;
        float Yn = Y + dY1 * STEP;
        float zn = z + STEP;

        // --- issue next step's transform + RI gather early ---
        float t0 = Yn * mc[0] + Xn * mc[3] + zn * mc[6] + mc[9];
        float t1 = Yn * mc[1] + Xn * mc[4] + zn * mc[7] + mc[10];
        float t2 = Yn * mc[2] + Xn * mc[5] + zn * mc[8] + mc[11];
        float nXv = t1, nYv = t0, nZv = t2;
        float nfX = fminf(fmaxf(rintf(nXv * 64.0f) + xr, 0.0f), 63.0f);
        float nfY = fminf(fmaxf(rintf(nYv * 64.0f) + yr, 0.0f), 63.0f);
        float nfZ = fminf(fmaxf(rintf(nZv * 64.0f) + zr, 0.0f), 63.0f);
        float2 ri_next = make_float2(0.f, 1.f);
        if (act) {
            int lin = ((int)nfY << 12) + ((int)nfX << 6) + (int)nfZ;
            ri_next = __ldg(&ri2[lin]);
        }

        // --- Gaussian mixture at CURRENT state using prefetched ri_cur ---
        float s_norm = 0.f, s_nus = 0.f, s_nx = 0.f, s_ny = 0.f,
              s_nz = 0.f, s_ndx = 0.f, s_ndy = 0.f, s_ndz = 0.f;
        if (act) {
            float dx  = cfX / 63.0f - cXv;
            float dy  = cfY / 63.0f - cYv;
            float dzv = cfZ / 63.0f - cZv;
            float A = ri_cur.x, sg = ri_cur.y;
            float inv_s2 = 1.0f / (sg * sg);
            float r2 = dx * dx + dy * dy + dzv * dzv;
            float ni = expf(-r2 * 0.5f * inv_s2) + 2e-7f;
            float nu = ni * A;
            float hx = dx * inv_s2, hy = dy * inv_s2, hz = dzv * inv_s2;
            s_norm = ni;       s_nus = nu;
            s_nx = nu * hx;    s_ny = nu * hy;    s_nz = nu * hz;
            s_ndx = ni * hx;   s_ndy = ni * hy;   s_ndz = ni * hz;
        }
#pragma unroll
        for (int off = 16; off > 0; off >>= 1) {
            s_norm += __shfl_xor_sync(0xffffffffu, s_norm, off);
            s_nus  += __shfl_xor_sync(0xffffffffu, s_nus,  off);
            s_nx   += __shfl_xor_sync(0xffffffffu, s_nx,   off);
            s_ny   += __shfl_xor_sync(0xffffffffu, s_ny,   off);
            s_nz   += __shfl_xor_sync(0xffffffffu, s_nz,   off);
            s_ndx  += __shfl_xor_sync(0xffffffffu, s_ndx,  off);
            s_ndy  += __shfl_xor_sync(0xffffffffu, s_ndy,  off);
            s_ndz  += __shfl_xor_sync(0xffffffffu, s_ndz,  off);
        }
        float n = s_nus / s_norm;
        float inv_n2 = 1.0f / (s_norm * s_norm);
        float nx = (s_norm * s_nx - s_nus * s_ndx) * inv_n2;
        float ny = (s_norm * s_ny - s_nus * s_ndy) * inv_n2;
        float nz = (s_norm * s_nz - s_nus * s_ndz) * inv_n2;

        float d0 = ny * md[0] + nx * md[3] + nz * md[6] + md[9];
        float d1 = ny * md[1] + nx * md[4] + nz * md[7] + md[10];
        float d2 = ny * md[2] + nx * md[5] + nz * md[8] + md[11];
        float dndx = d1, dndz = d2, dndy = d0;

        float dX2 = (dndx - dndz * dX1) * (1.0f + dX1 * dX1) / n;
        float dY2 = (dndy - dndz * dY1) * (1.0f + dY1 * dY1) / n;

        dX1 += dX2 * STEP;
        dY1 += dY2 * STEP;
        X = Xn; Y = Yn; z = zn;

        if (lane == 0) {
            gMX[ray * NS + s] = 2.0f * X - 1.0f;
            gMY[ray * NS + s] = 2.0f * Y - 1.0f;
            gMZ[ray * NS + s] = 2.0f * z - 1.0f;
        }

        cXv = nXv; cYv = nYv; cZv = nZv;
        cfX = nfX; cfY = nfY; cfZ = nfZ;
        ri_cur = ri_next;
    }
}

// ---------------- phase 2: fused trilinear resize (64^3 -> 192^3) + grid_sample ----------------
__device__ __forceinline__ float tri_interp(const float* __restrict__ m, int base,
                                            float wi, float wj, float ws) {
    float u = 1.0f - wi, v = 1.0f - wj, w = 1.0f - ws;
    float g00 = m[base]        * u + m[base + 4096]      * wi;
    float g10 = m[base + 64]   * u + m[base + 4160]      * wi;
    float g01 = m[base + 1]    * u + m[base + 4097]      * wi;
    float g11 = m[base + 65]   * u + m[base + 4161]      * wi;
    float h0  = g00 * v + g10 * wj;
    float h1  = g01 * v + g11 * wj;
    return h0 * w + h1 * ws;
}

__global__ void __launch_bounds__(256) sample_kernel(const float* __restrict__ vol,
                                                     float* __restrict__ out) {
    int idx = blockIdx.x * blockDim.x + threadIdx.x;
    if (idx >= OUT3) return;
    int cc = idx % OUTN;
    int bb = (idx / OUTN) % OUTN;
    int aa = idx / (OUTN * OUTN);

    const float scale = 63.0f / 191.0f;
    float pa = (float)aa * scale; int i0 = min((int)pa, 62); float wi = pa - (float)i0;
    float pb = (float)bb * scale; int j0 = min((int)pb, 62); float wj = pb - (float)j0;
    float pc = (float)cc * scale; int s0 = min((int)pc, 62); float ws = pc - (float)s0;
    int base = (i0 << 12) + (j0 << 6) + s0;

    float gx = tri_interp(gMX, base, wi, wj, ws);
    float gy = tri_interp(gMY, base, wi, wj, ws);
    float gz = tri_interp(gMZ, base, wi, wj, ws);

    float ix = (gx + 1.0f) * 0.5f * 191.0f;
    float iy = (gy + 1.0f) * 0.5f * 191.0f;
    float iz = (gz + 1.0f) * 0.5f * 191.0f;
    float x0 = floorf(ix), y0 = floorf(iy), z0 = floorf(iz);
    float fx = ix - x0, fy = iy - y0, fz = iz - z0;

    float res = 0.0f;
#pragma unroll
    for (int dz = 0; dz < 2; dz++)
#pragma unroll
        for (int dy = 0; dy < 2; dy++)
#pragma unroll
            for (int dx = 0; dx < 2; dx++) {
                float xi = x0 + (float)dx, yi = y0 + (float)dy, zi = z0 + (float)dz;
                bool inb = (xi >= 0.0f) && (xi <= 191.0f) &&
                           (yi >= 0.0f) && (yi <= 191.0f) &&
                           (zi >= 0.0f) && (zi <= 191.0f);
                float wgt = (dx ? fx : 1.0f - fx) * (dy ? fy : 1.0f - fy) * (dz ? fz : 1.0f - fz);
                int xc = (int)fminf(fmaxf(xi, 0.0f), 191.0f);
                int yc = (int)fminf(fmaxf(yi, 0.0f), 191.0f);
                int zc = (int)fminf(fmaxf(zi, 0.0f), 191.0f);
                if (inb) res += wgt * __ldg(&vol[(zc * OUTN + yc) * OUTN + xc]);
            }
    out[idx] = res;
}

// ---------------- launch ----------------
extern "C" void kernel_launch(void* const* d_in, const int* in_sizes, int n_in,
                              void* d_out, int out_size) {
    const float* phantom = nullptr;
    const float* RI      = nullptr;
    const float* ray0    = nullptr;
    for (int i = 0; i < n_in; i++) {
        if      (in_sizes[i] == OUT3)                phantom = (const float*)d_in[i];
        else if (in_sizes[i] == KGRID*KGRID*KGRID*2) RI      = (const float*)d_in[i];
        else if (in_sizes[i] == NRAY2 * 5)           ray0    = (const float*)d_in[i];
    }
    float* out = (float*)d_out;

    ray_kernel<<<(NRAY2 * 32) / 256, 256>>>(RI, ray0);
    sample_kernel<<<(OUT3 + 255) / 256, 256>>>(phantom, out);
}

// round 4
// speedup vs baseline: 1.4953x; 1.4260x over previous
#include <cuda_runtime.h>
#include <math.h>

#define KGRID 64
#define NRAY2 4096
#define NS    64
#define OUTN  192
#define OUT3  (OUTN*OUTN*OUTN)

// ---------------- scratch ----------------
__device__ float gMX[NRAY2 * NS];
__device__ float gMY[NRAY2 * NS];
__device__ float gMZ[NRAY2 * NS];

// ---------------- compile-time matrices ----------------
constexpr double c_sin(double x) {
    double x2 = x * x;
    return x * (1.0 + x2 * (-1.0/6.0 + x2 * (1.0/120.0 + x2 * (-1.0/5040.0
             + x2 * (1.0/362880.0 + x2 * (-1.0/39916800.0))))));
}
constexpr double c_cos(double x) {
    double x2 = x * x;
    return 1.0 + x2 * (-0.5 + x2 * (1.0/24.0 + x2 * (-1.0/720.0
             + x2 * (1.0/40320.0 + x2 * (-1.0/3628800.0 + x2 * (1.0/479001600.0))))));
}
struct M4 { double a[16]; };
constexpr M4 c_mul(const M4& A, const M4& B) {
    M4 C{};
    for (int i = 0; i < 4; i++)
        for (int j = 0; j < 4; j++) {
            double s = 0.0;
            for (int k = 0; k < 4; k++) s += A.a[i*4+k] * B.a[k*4+j];
            C.a[i*4+j] = s;
        }
    return C;
}
constexpr M4 c_ry(double t) { double c=c_cos(t), s=c_sin(t); return M4{{1,0,0,0, 0,c,-s,0, 0,s,c,0, 0,0,0,1}}; }
constexpr M4 c_rx(double t) { double c=c_cos(t), s=c_sin(t); return M4{{c,0,-s,0, 0,1,0,0, s,0,c,0, 0,0,0,1}}; }
constexpr M4 c_rz(double t) { double c=c_cos(t), s=c_sin(t); return M4{{c,-s,0,0, s,c,0,0, 0,0,1,0, 0,0,0,1}}; }
struct Mats { float mc[12]; float md[12]; };
constexpr Mats build_mats() {
    const double TX = 0.1, TY = 0.05, TZ = 0.02, CX = 0.5;
    M4 RY  = c_ry(-TY), RY_ = c_ry( TY);
    M4 RX  = c_rx( TX), RX_ = c_rx(-TX);
    M4 RZ  = c_rz(-TZ), RZ_ = c_rz( TZ);
    M4 S1{{1,0,0,0, 0,1,0,0, 0,0,1,0, -CX,-CX,-CX,1}};
    M4 S2{{1,0,0,0, 0,1,0,0, 0,0,1,0,  CX, CX, CX,1}};
    M4 M_crd = c_mul(c_mul(c_mul(c_mul(S1, RZ), RY), RX), S2);
    M4 M_drv = c_mul(c_mul(RX_, RY_), RZ_);
    Mats r{};
    for (int i = 0; i < 4; i++)
        for (int j = 0; j < 3; j++) {
            r.mc[i*3+j] = (float)M_crd.a[i*4+j];
            r.md[i*3+j] = (float)M_drv.a[i*4+j];
        }
    return r;
}
__constant__ Mats cMat = build_mats();

// ---------------- phase 1: ray tracing ----------------
// 8 lanes per ray (4 rays/warp). Lane l handles neighbors m = l + 8k, k=0..3
// (m < 27). Reduction = 3 butterfly rounds within the 8-lane group instead of
// 5 across the warp: total SHFL ops drop 6.7x vs the 1-warp/ray version
// (which was MIO/SHFL-throughput bound). RI gathers for the next step are
// issued before the current step's reduce chain.
__global__ void __launch_bounds__(128) ray_kernel(const float* __restrict__ RI,
                                                  const float* __restrict__ ray0) {
    int gtid = blockIdx.x * blockDim.x + threadIdx.x;
    int lane = gtid & 31;
    int grp  = (lane >> 3);          // 0..3 within warp
    int l    = lane & 7;             // 0..7 within group
    int ray  = (gtid >> 5) * 4 + grp;
    if (ray >= NRAY2) return;

    float mc[12], md[12];
#pragma unroll
    for (int i = 0; i < 12; i++) { mc[i] = cMat.mc[i]; md[i] = cMat.md[i]; }

    const float* r0 = ray0 + ray * 5;
    float X = r0[0], dX1 = r0[1], Y = r0[2], dY1 = r0[3], z = r0[4];

    float xr[4], yr[4], zr[4];
    bool  act[4];
#pragma unroll
    for (int k = 0; k < 4; k++) {
        int m = l + 8 * k;
        act[k] = (m < 27);
        int mm = act[k] ? m : 0;
        xr[k] = (float)((mm / 3) % 3 - 1);
        yr[k] = (float)(mm / 9 - 1);
        zr[k] = (float)(mm % 3 - 1);
    }

    const float2* ri2 = (const float2*)RI;
    const float STEP = 1.0f / 63.0f;

    if (l == 0) {
        gMX[ray * NS] = 2.0f * X - 1.0f;
        gMY[ray * NS] = 2.0f * Y - 1.0f;
        gMZ[ray * NS] = 2.0f * z - 1.0f;
    }

    float cXv, cYv, cZv;
    float cfX[4], cfY[4], cfZ[4];
    float2 ri_cur[4];
    {
        float t0 = Y * mc[0] + X * mc[3] + z * mc[6] + mc[9];
        float t1 = Y * mc[1] + X * mc[4] + z * mc[7] + mc[10];
        float t2 = Y * mc[2] + X * mc[5] + z * mc[8] + mc[11];
        cXv = t1; cYv = t0; cZv = t2;
        float rX = rintf(cXv * 64.0f), rY = rintf(cYv * 64.0f), rZ = rintf(cZv * 64.0f);
#pragma unroll
        for (int k = 0; k < 4; k++) {
            cfX[k] = fminf(fmaxf(rX + xr[k], 0.0f), 63.0f);
            cfY[k] = fminf(fmaxf(rY + yr[k], 0.0f), 63.0f);
            cfZ[k] = fminf(fmaxf(rZ + zr[k], 0.0f), 63.0f);
            ri_cur[k] = make_float2(0.f, 1.f);
            if (act[k]) {
                int lin = ((int)cfY[k] << 12) + ((int)cfX[k] << 6) + (int)cfZ[k];
                ri_cur[k] = __ldg(&ri2[lin]);
            }
        }
    }

    for (int s = 1; s < NS; s++) {
        // next-state position (depends only on current state, not the mixture)
        float Xn = X + dX1 * STEP;
        float Yn = Y + dY1 * STEP;
        float zn = z + STEP;

        // issue next step's transform + gathers early
        float t0 = Yn * mc[0] + Xn * mc[3] + zn * mc[6] + mc[9];
        float t1 = Yn * mc[1] + Xn * mc[4] + zn * mc[7] + mc[10];
        float t2 = Yn * mc[2] + Xn * mc[5] + zn * mc[8] + mc[11];
        float nXv = t1, nYv = t0, nZv = t2;
        float rX = rintf(nXv * 64.0f), rY = rintf(nYv * 64.0f), rZ = rintf(nZv * 64.0f);
        float nfX[4], nfY[4], nfZ[4];
        float2 ri_next[4];
#pragma unroll
        for (int k = 0; k < 4; k++) {
            nfX[k] = fminf(fmaxf(rX + xr[k], 0.0f), 63.0f);
            nfY[k] = fminf(fmaxf(rY + yr[k], 0.0f), 63.0f);
            nfZ[k] = fminf(fmaxf(rZ + zr[k], 0.0f), 63.0f);
            ri_next[k] = make_float2(0.f, 1.f);
            if (act[k]) {
                int lin = ((int)nfY[k] << 12) + ((int)nfX[k] << 6) + (int)nfZ[k];
                ri_next[k] = __ldg(&ri2[lin]);
            }
        }

        // Gaussian mixture at CURRENT state (4 neighbors per lane, local acc)
        float s_norm = 0.f, s_nus = 0.f, s_nx = 0.f, s_ny = 0.f,
              s_nz = 0.f, s_ndx = 0.f, s_ndy = 0.f, s_ndz = 0.f;
#pragma unroll
        for (int k = 0; k < 4; k++) {
            if (act[k]) {
                float dx  = cfX[k] / 63.0f - cXv;
                float dy  = cfY[k] / 63.0f - cYv;
                float dzv = cfZ[k] / 63.0f - cZv;
                float A = ri_cur[k].x, sg = ri_cur[k].y;
                float inv_s2 = 1.0f / (sg * sg);
                float r2 = dx * dx + dy * dy + dzv * dzv;
                float ni = expf(-r2 * 0.5f * inv_s2) + 2e-7f;
                float nu = ni * A;
                float hx = dx * inv_s2, hy = dy * inv_s2, hz = dzv * inv_s2;
                s_norm += ni;      s_nus += nu;
                s_nx += nu * hx;   s_ny += nu * hy;   s_nz += nu * hz;
                s_ndx += ni * hx;  s_ndy += ni * hy;  s_ndz += ni * hz;
            }
        }
        // reduce across the 8-lane group (xor 1,2,4 stays in-group)
#pragma unroll
        for (int off = 4; off > 0; off >>= 1) {
            s_norm += __shfl_xor_sync(0xffffffffu, s_norm, off);
            s_nus  += __shfl_xor_sync(0xffffffffu, s_nus,  off);
            s_nx   += __shfl_xor_sync(0xffffffffu, s_nx,   off);
            s_ny   += __shfl_xor_sync(0xffffffffu, s_ny,   off);
            s_nz   += __shfl_xor_sync(0xffffffffu, s_nz,   off);
            s_ndx  += __shfl_xor_sync(0xffffffffu, s_ndx,  off);
            s_ndy  += __shfl_xor_sync(0xffffffffu, s_ndy,  off);
            s_ndz  += __shfl_xor_sync(0xffffffffu, s_ndz,  off);
        }
        float n = s_nus / s_norm;
        float inv_n2 = 1.0f / (s_norm * s_norm);
        float nx = (s_norm * s_nx - s_nus * s_ndx) * inv_n2;
        float ny = (s_norm * s_ny - s_nus * s_ndy) * inv_n2;
        float nz = (s_norm * s_nz - s_nus * s_ndz) * inv_n2;

        float d0 = ny * md[0] + nx * md[3] + nz * md[6] + md[9];
        float d1 = ny * md[1] + nx * md[4] + nz * md[7] + md[10];
        float d2 = ny * md[2] + nx * md[5] + nz * md[8] + md[11];
        float dndx = d1, dndz = d2, dndy = d0;

        float dX2 = (dndx - dndz * dX1) * (1.0f + dX1 * dX1) / n;
        float dY2 = (dndy - dndz * dY1) * (1.0f + dY1 * dY1) / n;

        dX1 += dX2 * STEP;
        dY1 += dY2 * STEP;
        X = Xn; Y = Yn; z = zn;

        if (l == 0) {
            gMX[ray * NS + s] = 2.0f * X - 1.0f;
            gMY[ray * NS + s] = 2.0f * Y - 1.0f;
            gMZ[ray * NS + s] = 2.0f * z - 1.0f;
        }

        cXv = nXv; cYv = nYv; cZv = nZv;
#pragma unroll
        for (int k = 0; k < 4; k++) {
            cfX[k] = nfX[k]; cfY[k] = nfY[k]; cfZ[k] = nfZ[k];
            ri_cur[k] = ri_next[k];
        }
    }
}

// ---------------- phase 2: one warp per (aa,bb) output row ----------------
// The resize along aa/bb is fixed per row: precompute the bilinear row
// G[3][64] into smem once (coalesced), then each thread produces 6
// consecutive cc outputs. iz advances by ~1 per cc, so the z1 tap plane of
// output cc is the z0 plane of output cc+1: register-cache it.
__device__ __forceinline__ float4 load_plane(const float* __restrict__ vol,
                                             float x0f, float y0f, float zf) {
    bool zin  = (zf  >= 0.0f) && (zf  <= 191.0f);
    bool x0in = (x0f >= 0.0f) && (x0f <= 191.0f);
    bool x1in = (x0f + 1.0f >= 0.0f) && (x0f + 1.0f <= 191.0f);
    bool y0in = (y0f >= 0.0f) && (y0f <= 191.0f);
    bool y1in = (y0f + 1.0f >= 0.0f) && (y0f + 1.0f <= 191.0f);
    int zc  = (int)fminf(fmaxf(zf,  0.0f), 191.0f);
    int xc0 = (int)fminf(fmaxf(x0f, 0.0f), 191.0f);
    int xc1 = (int)fminf(fmaxf(x0f + 1.0f, 0.0f), 191.0f);
    int yc0 = (int)fminf(fmaxf(y0f, 0.0f), 191.0f);
    int yc1 = (int)fminf(fmaxf(y0f + 1.0f, 0.0f), 191.0f);
    int b0 = (zc * OUTN + yc0) * OUTN;
    int b1 = (zc * OUTN + yc1) * OUTN;
    float4 r;
    r.x = (zin && x0in && y0in) ? __ldg(&vol[b0 + xc0]) : 0.0f;
    r.y = (zin && x1in && y0in) ? __ldg(&vol[b0 + xc1]) : 0.0f;
    r.z = (zin && x0in && y1in) ? __ldg(&vol[b1 + xc0]) : 0.0f;
    r.w = (zin && x1in && y1in) ? __ldg(&vol[b1 + xc1]) : 0.0f;
    return r;
}

__global__ void __launch_bounds__(32) sample_kernel(const float* __restrict__ vol,
                                                    float* __restrict__ out) {
    int row = blockIdx.x;                 // 0..36863
    int aa = row / OUTN, bb = row % OUTN;
    __shared__ float Gx[64], Gy[64], Gz[64];

    const float scale = 63.0f / 191.0f;
    float pa = (float)aa * scale; int i0 = min((int)pa, 62); float wi = pa - (float)i0;
    float pb = (float)bb * scale; int j0 = min((int)pb, 62); float wj = pb - (float)j0;
    float u = 1.0f - wi, v = 1.0f - wj;
    int base = (i0 << 12) + (j0 << 6);

    int t = threadIdx.x;
#pragma unroll
    for (int sb = 0; sb < 2; sb++) {
        int s = t + sb * 32;
        {
            float a00 = gMX[base + s],        a10 = gMX[base + 4096 + s];
            float a01 = gMX[base + 64 + s],   a11 = gMX[base + 4160 + s];
            Gx[s] = (a00 * u + a10 * wi) * v + (a01 * u + a11 * wi) * wj;
        }
        {
            float a00 = gMY[base + s],        a10 = gMY[base + 4096 + s];
            float a01 = gMY[base + 64 + s],   a11 = gMY[base + 4160 + s];
            Gy[s] = (a00 * u + a10 * wi) * v + (a01 * u + a11 * wi) * wj;
        }
        {
            float a00 = gMZ[base + s],        a10 = gMZ[base + 4096 + s];
            float a01 = gMZ[base + 64 + s],   a11 = gMZ[base + 4160 + s];
            Gz[s] = (a00 * u + a10 * wi) * v + (a01 * u + a11 * wi) * wj;
        }
    }
    __syncwarp();

    float px0f = -1e9f, py0f = -1e9f, pz0f = -1e9f;
    float4 pl0 = make_float4(0.f, 0.f, 0.f, 0.f), pl1 = pl0;
    int obase = row * OUTN + t * 6;

#pragma unroll
    for (int q = 0; q < 6; q++) {
        int cc = t * 6 + q;
        float pc = (float)cc * scale; int s0 = min((int)pc, 62); float ws = pc - (float)s0;
        float gx = Gx[s0] * (1.0f - ws) + Gx[s0 + 1] * ws;
        float gy = Gy[s0] * (1.0f - ws) + Gy[s0 + 1] * ws;
        float gz = Gz[s0] * (1.0f - ws) + Gz[s0 + 1] * ws;

        float ix = (gx + 1.0f) * 0.5f * 191.0f;
        float iy = (gy + 1.0f) * 0.5f * 191.0f;
        float iz = (gz + 1.0f) * 0.5f * 191.0f;
        float x0f = floorf(ix), y0f = floorf(iy), z0f = floorf(iz);
        float fx = ix - x0f, fy = iy - y0f, fz = iz - z0f;

        bool samexy = (x0f == px0f) && (y0f == py0f);
        if (samexy && z0f == pz0f + 1.0f) {
            pl0 = pl1;
            pl1 = load_plane(vol, x0f, y0f, z0f + 1.0f);
        } else if (!(samexy && z0f == pz0f)) {
            pl0 = load_plane(vol, x0f, y0f, z0f);
            pl1 = load_plane(vol, x0f, y0f, z0f + 1.0f);
        }
        px0f = x0f; py0f = y0f; pz0f = z0f;

        float ux = 1.0f - fx, uy = 1.0f - fy;
        float r0 = uy * (ux * pl0.x + fx * pl0.y) + fy * (ux * pl0.z + fx * pl0.w);
        float r1 = uy * (ux * pl1.x + fx * pl1.y) + fy * (ux * pl1.z + fx * pl1.w);
        out[obase + q] = r0 * (1.0f - fz) + r1 * fz;
    }
}

// ---------------- launch ----------------
extern "C" void kernel_launch(void* const* d_in, const int* in_sizes, int n_in,
                              void* d_out, int out_size) {
    const float* phantom = nullptr;
    const float* RI      = nullptr;
    const float* ray0    = nullptr;
    for (int i = 0; i < n_in; i++) {
        if      (in_sizes[i] == OUT3)                phantom = (const float*)d_in[i];
        else if (in_sizes[i] == KGRID*KGRID*KGRID*2) RI      = (const float*)d_in[i];
        else if (in_sizes[i] == NRAY2 * 5)           ray0    = (const float*)d_in[i];
    }
    float* out = (float*)d_out;

    ray_kernel<<<(NRAY2 * 8) / 128, 128>>>(RI, ray0);
    sample_kernel<<<OUTN * OUTN, 32>>>(phantom, out);
}

// round 5
// speedup vs baseline: 2.0392x; 1.3638x over previous
#include <cuda_runtime.h>
#include <math.h>

#define KGRID 64
#define NRAY2 4096
#define NS    64
#define OUTN  192
#define OUT3  (OUTN*OUTN*OUTN)

// ---------------- scratch ----------------
__device__ float gMX[NRAY2 * NS];
__device__ float gMY[NRAY2 * NS];
__device__ float gMZ[NRAY2 * NS];

// ---------------- compile-time matrices ----------------
constexpr double c_sin(double x) {
    double x2 = x * x;
    return x * (1.0 + x2 * (-1.0/6.0 + x2 * (1.0/120.0 + x2 * (-1.0/5040.0
             + x2 * (1.0/362880.0 + x2 * (-1.0/39916800.0))))));
}
constexpr double c_cos(double x) {
    double x2 = x * x;
    return 1.0 + x2 * (-0.5 + x2 * (1.0/24.0 + x2 * (-1.0/720.0
             + x2 * (1.0/40320.0 + x2 * (-1.0/3628800.0 + x2 * (1.0/479001600.0))))));
}
struct M4 { double a[16]; };
constexpr M4 c_mul(const M4& A, const M4& B) {
    M4 C{};
    for (int i = 0; i < 4; i++)
        for (int j = 0; j < 4; j++) {
            double s = 0.0;
            for (int k = 0; k < 4; k++) s += A.a[i*4+k] * B.a[k*4+j];
            C.a[i*4+j] = s;
        }
    return C;
}
constexpr M4 c_ry(double t) { double c=c_cos(t), s=c_sin(t); return M4{{1,0,0,0, 0,c,-s,0, 0,s,c,0, 0,0,0,1}}; }
constexpr M4 c_rx(double t) { double c=c_cos(t), s=c_sin(t); return M4{{c,0,-s,0, 0,1,0,0, s,0,c,0, 0,0,0,1}}; }
constexpr M4 c_rz(double t) { double c=c_cos(t), s=c_sin(t); return M4{{c,-s,0,0, s,c,0,0, 0,0,1,0, 0,0,0,1}}; }
struct Mats { float mc[12]; float md[12]; };
constexpr Mats build_mats() {
    const double TX = 0.1, TY = 0.05, TZ = 0.02, CX = 0.5;
    M4 RY  = c_ry(-TY), RY_ = c_ry( TY);
    M4 RX  = c_rx( TX), RX_ = c_rx(-TX);
    M4 RZ  = c_rz(-TZ), RZ_ = c_rz( TZ);
    M4 S1{{1,0,0,0, 0,1,0,0, 0,0,1,0, -CX,-CX,-CX,1}};
    M4 S2{{1,0,0,0, 0,1,0,0, 0,0,1,0,  CX, CX, CX,1}};
    M4 M_crd = c_mul(c_mul(c_mul(c_mul(S1, RZ), RY), RX), S2);
    M4 M_drv = c_mul(c_mul(RX_, RY_), RZ_);
    Mats r{};
    for (int i = 0; i < 4; i++)
        for (int j = 0; j < 3; j++) {
            r.mc[i*3+j] = (float)M_crd.a[i*4+j];
            r.md[i*3+j] = (float)M_drv.a[i*4+j];
        }
    return r;
}
__constant__ Mats cMat = build_mats();

// ---------------- phase 1: ray tracing ----------------
// 8 lanes per ray (4 rays/warp), fast-math inner loop (__expf, __fdividef,
// mul-by-1/63). The per-step serial chain (not SHFL throughput) is the
// binding constraint at 1024 warps, so cutting instruction count AND the
// div/exp latency chains is what matters.
__global__ void __launch_bounds__(64) ray_kernel(const float* __restrict__ RI,
                                                 const float* __restrict__ ray0) {
    int gtid = blockIdx.x * blockDim.x + threadIdx.x;
    int lane = gtid & 31;
    int grp  = (lane >> 3);
    int l    = lane & 7;
    int ray  = (gtid >> 5) * 4 + grp;
    if (ray >= NRAY2) return;

    float mc[12], md[12];
#pragma unroll
    for (int i = 0; i < 12; i++) { mc[i] = cMat.mc[i]; md[i] = cMat.md[i]; }

    const float* r0 = ray0 + ray * 5;
    float X = r0[0], dX1 = r0[1], Y = r0[2], dY1 = r0[3], z = r0[4];

    float xr[4], yr[4], zr[4];
    bool  act[4];
#pragma unroll
    for (int k = 0; k < 4; k++) {
        int m = l + 8 * k;
        act[k] = (m < 27);
        int mm = act[k] ? m : 0;
        xr[k] = (float)((mm / 3) % 3 - 1);
        yr[k] = (float)(mm / 9 - 1);
        zr[k] = (float)(mm % 3 - 1);
    }

    const float2* ri2 = (const float2*)RI;
    const float STEP  = 1.0f / 63.0f;
    const float INV63 = 1.0f / 63.0f;

    if (l == 0) {
        gMX[ray * NS] = 2.0f * X - 1.0f;
        gMY[ray * NS] = 2.0f * Y - 1.0f;
        gMZ[ray * NS] = 2.0f * z - 1.0f;
    }

    float cXv, cYv, cZv;
    float cfX[4], cfY[4], cfZ[4];
    float2 ri_cur[4];
    {
        float t0 = Y * mc[0] + X * mc[3] + z * mc[6] + mc[9];
        float t1 = Y * mc[1] + X * mc[4] + z * mc[7] + mc[10];
        float t2 = Y * mc[2] + X * mc[5] + z * mc[8] + mc[11];
        cXv = t1; cYv = t0; cZv = t2;
        float rX = rintf(cXv * 64.0f), rY = rintf(cYv * 64.0f), rZ = rintf(cZv * 64.0f);
#pragma unroll
        for (int k = 0; k < 4; k++) {
            cfX[k] = fminf(fmaxf(rX + xr[k], 0.0f), 63.0f);
            cfY[k] = fminf(fmaxf(rY + yr[k], 0.0f), 63.0f);
            cfZ[k] = fminf(fmaxf(rZ + zr[k], 0.0f), 63.0f);
            ri_cur[k] = make_float2(0.f, 1.f);
            if (act[k]) {
                int lin = ((int)cfY[k] << 12) + ((int)cfX[k] << 6) + (int)cfZ[k];
                ri_cur[k] = __ldg(&ri2[lin]);
            }
        }
    }

    for (int s = 1; s < NS; s++) {
        float Xn = X + dX1 * STEP;
        float Yn = Y + dY1 * STEP;
        float zn = z + STEP;

        // next step's transform + gathers issued early
        float t0 = Yn * mc[0] + Xn * mc[3] + zn * mc[6] + mc[9];
        float t1 = Yn * mc[1] + Xn * mc[4] + zn * mc[7] + mc[10];
        float t2 = Yn * mc[2] + Xn * mc[5] + zn * mc[8] + mc[11];
        float nXv = t1, nYv = t0, nZv = t2;
        float rX = rintf(nXv * 64.0f), rY = rintf(nYv * 64.0f), rZ = rintf(nZv * 64.0f);
        float nfX[4], nfY[4], nfZ[4];
        float2 ri_next[4];
#pragma unroll
        for (int k = 0; k < 4; k++) {
            nfX[k] = fminf(fmaxf(rX + xr[k], 0.0f), 63.0f);
            nfY[k] = fminf(fmaxf(rY + yr[k], 0.0f), 63.0f);
            nfZ[k] = fminf(fmaxf(rZ + zr[k], 0.0f), 63.0f);
            ri_next[k] = make_float2(0.f, 1.f);
            if (act[k]) {
                int lin = ((int)nfY[k] << 12) + ((int)nfX[k] << 6) + (int)nfZ[k];
                ri_next[k] = __ldg(&ri2[lin]);
            }
        }

        float s_norm = 0.f, s_nus = 0.f, s_nx = 0.f, s_ny = 0.f,
              s_nz = 0.f, s_ndx = 0.f, s_ndy = 0.f, s_ndz = 0.f;
#pragma unroll
        for (int k = 0; k < 4; k++) {
            if (act[k]) {
                float dx  = cfX[k] * INV63 - cXv;
                float dy  = cfY[k] * INV63 - cYv;
                float dzv = cfZ[k] * INV63 - cZv;
                float A = ri_cur[k].x, sg = ri_cur[k].y;
                float inv_s2 = __fdividef(1.0f, sg * sg);
                float r2 = dx * dx + dy * dy + dzv * dzv;
                float ni = __expf(-r2 * 0.5f * inv_s2) + 2e-7f;
                float nu = ni * A;
                float hx = dx * inv_s2, hy = dy * inv_s2, hz = dzv * inv_s2;
                s_norm += ni;      s_nus += nu;
                s_nx += nu * hx;   s_ny += nu * hy;   s_nz += nu * hz;
                s_ndx += ni * hx;  s_ndy += ni * hy;  s_ndz += ni * hz;
            }
        }
#pragma unroll
        for (int off = 4; off > 0; off >>= 1) {
            s_norm += __shfl_xor_sync(0xffffffffu, s_norm, off);
            s_nus  += __shfl_xor_sync(0xffffffffu, s_nus,  off);
            s_nx   += __shfl_xor_sync(0xffffffffu, s_nx,   off);
            s_ny   += __shfl_xor_sync(0xffffffffu, s_ny,   off);
            s_nz   += __shfl_xor_sync(0xffffffffu, s_nz,   off);
            s_ndx  += __shfl_xor_sync(0xffffffffu, s_ndx,  off);
            s_ndy  += __shfl_xor_sync(0xffffffffu, s_ndy,  off);
            s_ndz  += __shfl_xor_sync(0xffffffffu, s_ndz,  off);
        }
        float inv_norm = __fdividef(1.0f, s_norm);
        float inv_n2 = inv_norm * inv_norm;
        float nx = (s_norm * s_nx - s_nus * s_ndx) * inv_n2;
        float ny = (s_norm * s_ny - s_nus * s_ndy) * inv_n2;
        float nz = (s_norm * s_nz - s_nus * s_ndz) * inv_n2;

        float d0 = ny * md[0] + nx * md[3] + nz * md[6] + md[9];
        float d1 = ny * md[1] + nx * md[4] + nz * md[7] + md[10];
        float d2 = ny * md[2] + nx * md[5] + nz * md[8] + md[11];
        float dndx = d1, dndz = d2, dndy = d0;

        float inv_n = __fdividef(s_norm, s_nus);   // 1/n
        float dX2 = (dndx - dndz * dX1) * (1.0f + dX1 * dX1) * inv_n;
        float dY2 = (dndy - dndz * dY1) * (1.0f + dY1 * dY1) * inv_n;

        dX1 += dX2 * STEP;
        dY1 += dY2 * STEP;
        X = Xn; Y = Yn; z = zn;

        if (l == 0) {
            gMX[ray * NS + s] = 2.0f * X - 1.0f;
            gMY[ray * NS + s] = 2.0f * Y - 1.0f;
            gMZ[ray * NS + s] = 2.0f * z - 1.0f;
        }

        cXv = nXv; cYv = nYv; cZv = nZv;
#pragma unroll
        for (int k = 0; k < 4; k++) {
            cfX[k] = nfX[k]; cfY[k] = nfY[k]; cfZ[k] = nfZ[k];
            ri_cur[k] = ri_next[k];
        }
    }
}

// ---------------- phase 2: one warp per (aa,bb) row, 4 rows per block ----------------
// Paired x-tap loads: one aligned float2 + predicated scalar fixup replaces
// two scalar LDGs (~25% fewer volume wavefronts at the L1, which is the
// binding constraint). Stores staged through smem for coalescing.
__device__ __forceinline__ float2 load_xpair(const float* __restrict__ vol, int idx) {
    float2 a = __ldg((const float2*)(vol + (idx & ~1)));
    if (idx & 1) { a.x = a.y; a.y = __ldg(vol + idx + 1); }
    return a;
}

// Plane of 4 taps at (x0..x0+1, y0..y0+1, z). Integer coords, unsigned bounds.
__device__ __forceinline__ float4 load_plane(const float* __restrict__ vol,
                                             int x0, int y0, int z) {
    bool zin  = ((unsigned)z  < 192u);
    bool x0in = ((unsigned)x0 < 192u);
    bool x1in = ((unsigned)(x0 + 1) < 192u);
    bool y0in = ((unsigned)y0 < 192u);
    bool y1in = ((unsigned)(y0 + 1) < 192u);
    int zc  = min(max(z, 0), 191);
    int xs  = min(max(x0, 0), 190);           // pair start: loads xs, xs+1 (always in-row)
    int yc0 = min(max(y0, 0), 191);
    int yc1 = min(max(y0 + 1, 0), 191);
    int b0 = (zc * OUTN + yc0) * OUTN;
    int b1 = (zc * OUTN + yc1) * OUTN;
    float2 p0 = load_xpair(vol, b0 + xs);
    float2 p1 = load_xpair(vol, b1 + xs);
    bool at = (x0 == xs);                     // false only when x0 clamped
    float t0a = at ? p0.x : p0.y;             // tap at x0   (x0=191 -> p.y)
    float t0b = at ? p0.y : p0.x;             // tap at x0+1 (x0=-1  -> p.x)
    float t1a = at ? p1.x : p1.y;
    float t1b = at ? p1.y : p1.x;
    float4 r;
    r.x = (zin && x0in && y0in) ? t0a : 0.0f;
    r.y = (zin && x1in && y0in) ? t0b : 0.0f;
    r.z = (zin && x0in && y1in) ? t1a : 0.0f;
    r.w = (zin && x1in && y1in) ? t1b : 0.0f;
    return r;
}

__global__ void __launch_bounds__(128) sample_kernel(const float* __restrict__ vol,
                                                     float* __restrict__ out) {
    int w = threadIdx.x >> 5;
    int t = threadIdx.x & 31;
    int row = blockIdx.x * 4 + w;             // 0..36863
    int aa = row / OUTN, bb = row % OUTN;

    __shared__ float Gx[4][64], Gy[4][64], Gz[4][64];
    __shared__ float Obuf[4][192];

    const float scale = 63.0f / 191.0f;
    float pa = (float)aa * scale; int i0 = min((int)pa, 62); float wi = pa - (float)i0;
    float pb = (float)bb * scale; int j0 = min((int)pb, 62); float wj = pb - (float)j0;
    float u = 1.0f - wi, v = 1.0f - wj;
    int base = (i0 << 12) + (j0 << 6);

#pragma unroll
    for (int sb = 0; sb < 2; sb++) {
        int s = t + sb * 32;
        {
            float a00 = gMX[base + s],      a10 = gMX[base + 4096 + s];
            float a01 = gMX[base + 64 + s], a11 = gMX[base + 4160 + s];
            Gx[w][s] = (a00 * u + a10 * wi) * v + (a01 * u + a11 * wi) * wj;
        }
        {
            float a00 = gMY[base + s],      a10 = gMY[base + 4096 + s];
            float a01 = gMY[base + 64 + s], a11 = gMY[base + 4160 + s];
            Gy[w][s] = (a00 * u + a10 * wi) * v + (a01 * u + a11 * wi) * wj;
        }
        {
            float a00 = gMZ[base + s],      a10 = gMZ[base + 4096 + s];
            float a01 = gMZ[base + 64 + s], a11 = gMZ[base + 4160 + s];
            Gz[w][s] = (a00 * u + a10 * wi) * v + (a01 * u + a11 * wi) * wj;
        }
    }
    __syncwarp();

    int px = 0x7fffffff, py = 0x7fffffff, pz = 0x7fffffff;
    float4 pl0 = make_float4(0.f, 0.f, 0.f, 0.f), pl1 = pl0;

#pragma unroll
    for (int q = 0; q < 6; q++) {
        int cc = t * 6 + q;
        float pc = (float)cc * scale; int s0 = min((int)pc, 62); float ws = pc - (float)s0;
        float gx = Gx[w][s0] * (1.0f - ws) + Gx[w][s0 + 1] * ws;
        float gy = Gy[w][s0] * (1.0f - ws) + Gy[w][s0 + 1] * ws;
        float gz = Gz[w][s0] * (1.0f - ws) + Gz[w][s0 + 1] * ws;

        float ix = (gx + 1.0f) * 0.5f * 191.0f;
        float iy = (gy + 1.0f) * 0.5f * 191.0f;
        float iz = (gz + 1.0f) * 0.5f * 191.0f;
        float xf = floorf(ix), yf = floorf(iy), zf = floorf(iz);
        float fx = ix - xf, fy = iy - yf, fz = iz - zf;
        int x0 = (int)xf, y0 = (int)yf, z0 = (int)zf;

        bool samexy = (x0 == px) && (y0 == py);
        if (samexy && z0 == pz + 1) {
            pl0 = pl1;
            pl1 = load_plane(vol, x0, y0, z0 + 1);
        } else if (!(samexy && z0 == pz)) {
            pl0 = load_plane(vol, x0, y0, z0);
            pl1 = load_plane(vol, x0, y0, z0 + 1);
        }
        px = x0; py = y0; pz = z0;

        float ux = 1.0f - fx, uy = 1.0f - fy;
        float r0 = uy * (ux * pl0.x + fx * pl0.y) + fy * (ux * pl0.z + fx * pl0.w);
        float r1 = uy * (ux * pl1.x + fx * pl1.y) + fy * (ux * pl1.z + fx * pl1.w);
        Obuf[w][cc] = r0 * (1.0f - fz) + r1 * fz;
    }
    __syncwarp();

    int obase = row * OUTN;
#pragma unroll
    for (int s = 0; s < 6; s++) out[obase + s * 32 + t] = Obuf[w][s * 32 + t];
}

// ---------------- launch ----------------
extern "C" void kernel_launch(void* const* d_in, const int* in_sizes, int n_in,
                              void* d_out, int out_size) {
    const float* phantom = nullptr;
    const float* RI      = nullptr;
    const float* ray0    = nullptr;
    for (int i = 0; i < n_in; i++) {
        if      (in_sizes[i] == OUT3)                phantom = (const float*)d_in[i];
        else if (in_sizes[i] == KGRID*KGRID*KGRID*2) RI      = (const float*)d_in[i];
        else if (in_sizes[i] == NRAY2 * 5)           ray0    = (const float*)d_in[i];
    }
    float* out = (float*)d_out;

    ray_kernel<<<(NRAY2 * 8) / 64, 64>>>(RI, ray0);
    sample_kernel<<<OUTN * OUTN / 4, 128>>>(phantom, out);
}

// round 6
// speedup vs baseline: 2.5496x; 1.2503x over previous
#include <cuda_runtime.h>
#include <math.h>

#define KGRID 64
#define NRAY2 4096
#define NS    64
#define OUTN  192
#define OUT3  (OUTN*OUTN*OUTN)

#define RAY_BLOCKS   256      // 16 rays/block at 128 threads
#define BUILD_BLOCKS 1792

// ---------------- scratch ----------------
__device__ float  gMX[NRAY2 * NS];
__device__ float  gMY[NRAY2 * NS];
__device__ float  gMZ[NRAY2 * NS];
__device__ float4 gVolP[OUT3];     // 2x2 packed taps: {v(y,x), v(y,x+1), v(y+1,x), v(y+1,x+1)}

// ---------------- compile-time matrices ----------------
constexpr double c_sin(double x) {
    double x2 = x * x;
    return x * (1.0 + x2 * (-1.0/6.0 + x2 * (1.0/120.0 + x2 * (-1.0/5040.0
             + x2 * (1.0/362880.0 + x2 * (-1.0/39916800.0))))));
}
constexpr double c_cos(double x) {
    double x2 = x * x;
    return 1.0 + x2 * (-0.5 + x2 * (1.0/24.0 + x2 * (-1.0/720.0
             + x2 * (1.0/40320.0 + x2 * (-1.0/3628800.0 + x2 * (1.0/479001600.0))))));
}
struct M4 { double a[16]; };
constexpr M4 c_mul(const M4& A, const M4& B) {
    M4 C{};
    for (int i = 0; i < 4; i++)
        for (int j = 0; j < 4; j++) {
            double s = 0.0;
            for (int k = 0; k < 4; k++) s += A.a[i*4+k] * B.a[k*4+j];
            C.a[i*4+j] = s;
        }
    return C;
}
constexpr M4 c_ry(double t) { double c=c_cos(t), s=c_sin(t); return M4{{1,0,0,0, 0,c,-s,0, 0,s,c,0, 0,0,0,1}}; }
constexpr M4 c_rx(double t) { double c=c_cos(t), s=c_sin(t); return M4{{c,0,-s,0, 0,1,0,0, s,0,c,0, 0,0,0,1}}; }
constexpr M4 c_rz(double t) { double c=c_cos(t), s=c_sin(t); return M4{{c,-s,0,0, s,c,0,0, 0,0,1,0, 0,0,0,1}}; }
struct Mats { float mc[12]; float md[12]; };
constexpr Mats build_mats() {
    const double TX = 0.1, TY = 0.05, TZ = 0.02, CX = 0.5;
    M4 RY  = c_ry(-TY), RY_ = c_ry( TY);
    M4 RX  = c_rx( TX), RX_ = c_rx(-TX);
    M4 RZ  = c_rz(-TZ), RZ_ = c_rz( TZ);
    M4 S1{{1,0,0,0, 0,1,0,0, 0,0,1,0, -CX,-CX,-CX,1}};
    M4 S2{{1,0,0,0, 0,1,0,0, 0,0,1,0,  CX, CX, CX,1}};
    M4 M_crd = c_mul(c_mul(c_mul(c_mul(S1, RZ), RY), RX), S2);
    M4 M_drv = c_mul(c_mul(RX_, RY_), RZ_);
    Mats r{};
    for (int i = 0; i < 4; i++)
        for (int j = 0; j < 3; j++) {
            r.mc[i*3+j] = (float)M_crd.a[i*4+j];
            r.md[i*3+j] = (float)M_drv.a[i*4+j];
        }
    return r;
}
__constant__ Mats cMat = build_mats();

// ---------------- ray-tracing body (8 lanes/ray, 4 rays/warp) ----------------
__device__ __forceinline__ void ray_body(const float* __restrict__ RI,
                                         const float* __restrict__ ray0,
                                         int warp_global, int lane) {
    int grp  = (lane >> 3);
    int l    = lane & 7;
    int ray  = warp_global * 4 + grp;
    if (ray >= NRAY2) return;

    float mc[12], md[12];
#pragma unroll
    for (int i = 0; i < 12; i++) { mc[i] = cMat.mc[i]; md[i] = cMat.md[i]; }

    const float* r0 = ray0 + ray * 5;
    float X = r0[0], dX1 = r0[1], Y = r0[2], dY1 = r0[3], z = r0[4];

    float xr[4], yr[4], zr[4];
    bool  act[4];
#pragma unroll
    for (int k = 0; k < 4; k++) {
        int m = l + 8 * k;
        act[k] = (m < 27);
        int mm = act[k] ? m : 0;
        xr[k] = (float)((mm / 3) % 3 - 1);
        yr[k] = (float)(mm / 9 - 1);
        zr[k] = (float)(mm % 3 - 1);
    }

    const float2* ri2 = (const float2*)RI;
    const float STEP  = 1.0f / 63.0f;
    const float INV63 = 1.0f / 63.0f;

    if (l == 0) {
        gMX[ray * NS] = 2.0f * X - 1.0f;
        gMY[ray * NS] = 2.0f * Y - 1.0f;
        gMZ[ray * NS] = 2.0f * z - 1.0f;
    }

    float cXv, cYv, cZv;
    float cfX[4], cfY[4], cfZ[4];
    float2 ri_cur[4];
    {
        float t0 = Y * mc[0] + X * mc[3] + z * mc[6] + mc[9];
        float t1 = Y * mc[1] + X * mc[4] + z * mc[7] + mc[10];
        float t2 = Y * mc[2] + X * mc[5] + z * mc[8] + mc[11];
        cXv = t1; cYv = t0; cZv = t2;
        float rX = rintf(cXv * 64.0f), rY = rintf(cYv * 64.0f), rZ = rintf(cZv * 64.0f);
#pragma unroll
        for (int k = 0; k < 4; k++) {
            cfX[k] = fminf(fmaxf(rX + xr[k], 0.0f), 63.0f);
            cfY[k] = fminf(fmaxf(rY + yr[k], 0.0f), 63.0f);
            cfZ[k] = fminf(fmaxf(rZ + zr[k], 0.0f), 63.0f);
            ri_cur[k] = make_float2(0.f, 1.f);
            if (act[k]) {
                int lin = ((int)cfY[k] << 12) + ((int)cfX[k] << 6) + (int)cfZ[k];
                ri_cur[k] = __ldg(&ri2[lin]);
            }
        }
    }

    for (int s = 1; s < NS; s++) {
        float Xn = X + dX1 * STEP;
        float Yn = Y + dY1 * STEP;
        float zn = z + STEP;

        float t0 = Yn * mc[0] + Xn * mc[3] + zn * mc[6] + mc[9];
        float t1 = Yn * mc[1] + Xn * mc[4] + zn * mc[7] + mc[10];
        float t2 = Yn * mc[2] + Xn * mc[5] + zn * mc[8] + mc[11];
        float nXv = t1, nYv = t0, nZv = t2;
        float rX = rintf(nXv * 64.0f), rY = rintf(nYv * 64.0f), rZ = rintf(nZv * 64.0f);
        float nfX[4], nfY[4], nfZ[4];
        float2 ri_next[4];
#pragma unroll
        for (int k = 0; k < 4; k++) {
            nfX[k] = fminf(fmaxf(rX + xr[k], 0.0f), 63.0f);
            nfY[k] = fminf(fmaxf(rY + yr[k], 0.0f), 63.0f);
            nfZ[k] = fminf(fmaxf(rZ + zr[k], 0.0f), 63.0f);
            ri_next[k] = make_float2(0.f, 1.f);
            if (act[k]) {
                int lin = ((int)nfY[k] << 12) + ((int)nfX[k] << 6) + (int)nfZ[k];
                ri_next[k] = __ldg(&ri2[lin]);
            }
        }

        float s_norm = 0.f, s_nus = 0.f, s_nx = 0.f, s_ny = 0.f,
              s_nz = 0.f, s_ndx = 0.f, s_ndy = 0.f, s_ndz = 0.f;
#pragma unroll
        for (int k = 0; k < 4; k++) {
            if (act[k]) {
                float dx  = cfX[k] * INV63 - cXv;
                float dy  = cfY[k] * INV63 - cYv;
                float dzv = cfZ[k] * INV63 - cZv;
                float A = ri_cur[k].x, sg = ri_cur[k].y;
                float inv_s2 = __fdividef(1.0f, sg * sg);
                float r2 = dx * dx + dy * dy + dzv * dzv;
                float ni = __expf(-r2 * 0.5f * inv_s2) + 2e-7f;
                float nu = ni * A;
                float hx = dx * inv_s2, hy = dy * inv_s2, hz = dzv * inv_s2;
                s_norm += ni;      s_nus += nu;
                s_nx += nu * hx;   s_ny += nu * hy;   s_nz += nu * hz;
                s_ndx += ni * hx;  s_ndy += ni * hy;  s_ndz += ni * hz;
            }
        }
#pragma unroll
        for (int off = 4; off > 0; off >>= 1) {
            s_norm += __shfl_xor_sync(0xffffffffu, s_norm, off);
            s_nus  += __shfl_xor_sync(0xffffffffu, s_nus,  off);
            s_nx   += __shfl_xor_sync(0xffffffffu, s_nx,   off);
            s_ny   += __shfl_xor_sync(0xffffffffu, s_ny,   off);
            s_nz   += __shfl_xor_sync(0xffffffffu, s_nz,   off);
            s_ndx  += __shfl_xor_sync(0xffffffffu, s_ndx,  off);
            s_ndy  += __shfl_xor_sync(0xffffffffu, s_ndy,  off);
            s_ndz  += __shfl_xor_sync(0xffffffffu, s_ndz,  off);
        }
        float inv_norm = __fdividef(1.0f, s_norm);
        float inv_n2 = inv_norm * inv_norm;
        float nx = (s_norm * s_nx - s_nus * s_ndx) * inv_n2;
        float ny = (s_norm * s_ny - s_nus * s_ndy) * inv_n2;
        float nz = (s_norm * s_nz - s_nus * s_ndz) * inv_n2;

        float d0 = ny * md[0] + nx * md[3] + nz * md[6] + md[9];
        float d1 = ny * md[1] + nx * md[4] + nz * md[7] + md[10];
        float d2 = ny * md[2] + nx * md[5] + nz * md[8] + md[11];
        float dndx = d1, dndz = d2, dndy = d0;

        float inv_n = __fdividef(s_norm, s_nus);
        float dX2 = (dndx - dndz * dX1) * (1.0f + dX1 * dX1) * inv_n;
        float dY2 = (dndy - dndz * dY1) * (1.0f + dY1 * dY1) * inv_n;

        dX1 += dX2 * STEP;
        dY1 += dY2 * STEP;
        X = Xn; Y = Yn; z = zn;

        if (l == 0) {
            gMX[ray * NS + s] = 2.0f * X - 1.0f;
            gMY[ray * NS + s] = 2.0f * Y - 1.0f;
            gMZ[ray * NS + s] = 2.0f * z - 1.0f;
        }

        cXv = nXv; cYv = nYv; cZv = nZv;
#pragma unroll
        for (int k = 0; k < 4; k++) {
            cfX[k] = nfX[k]; cfY[k] = nfY[k]; cfZ[k] = nfZ[k];
            ri_cur[k] = ri_next[k];
        }
    }
}

// ---------------- fused kernel: rays (blocks 0..255) + volP build (rest) ----------------
// Build is pure DRAM streaming (~170 MB); ray part is latency/ALU-bound on
// few warps. Running them in one grid overlaps them nearly perfectly.
__global__ void __launch_bounds__(128) ray_build_kernel(const float* __restrict__ RI,
                                                        const float* __restrict__ ray0,
                                                        const float* __restrict__ vol) {
    if (blockIdx.x < RAY_BLOCKS) {
        int warp_global = blockIdx.x * 4 + (threadIdx.x >> 5);
        ray_body(RI, ray0, warp_global, threadIdx.x & 31);
        return;
    }
    // volP build: edge-replicated 2x2 packing
    int tid0   = (blockIdx.x - RAY_BLOCKS) * 128 + threadIdx.x;
    int stride = BUILD_BLOCKS * 128;
    for (int idx = tid0; idx < OUT3; idx += stride) {
        int x = idx % OUTN;
        int y = (idx / OUTN) % OUTN;
        int zrow = idx / (OUTN * OUTN);   // z
        int x1 = min(x + 1, OUTN - 1);
        int y1 = min(y + 1, OUTN - 1);
        const float* p0 = vol + (zrow * OUTN + y) * OUTN;
        const float* p1 = vol + (zrow * OUTN + y1) * OUTN;
        gVolP[idx] = make_float4(__ldg(p0 + x), __ldg(p0 + x1),
                                 __ldg(p1 + x), __ldg(p1 + x1));
    }
}

// ---------------- phase 2: one warp per (aa,bb) row, 4 rows/block ----------------
// One LDG.128 from gVolP fetches all 4 taps of a z-plane. z-register-cache
// keeps it at ~1 load per output.
__device__ __forceinline__ float4 load_plane(int x0, int y0, int z) {
    bool zin  = ((unsigned)z        < 192u);
    bool x0in = ((unsigned)x0       < 192u);
    bool x1in = ((unsigned)(x0 + 1) < 192u);
    bool y0in = ((unsigned)y0       < 192u);
    bool y1in = ((unsigned)(y0 + 1) < 192u);
    int zc = min(max(z, 0), 191);
    int xs = min(max(x0, 0), 191);
    int ys = min(max(y0, 0), 191);
    float4 p = __ldg(&gVolP[(zc * OUTN + ys) * OUTN + xs]);
    bool ax = (x0 >= 0), ay = (y0 >= 0);
    // remap for the clamped-base case (x0==-1 / y0==-1): valid tap sits at base
    float t00 = p.x;
    float t01 = ax ? p.y : p.x;
    float t10 = ay ? p.z : p.x;
    float t11 = ax ? (ay ? p.w : p.y) : (ay ? p.z : p.x);
    float4 r;
    r.x = (zin && x0in && y0in) ? t00 : 0.0f;
    r.y = (zin && x1in && y0in) ? t01 : 0.0f;
    r.z = (zin && x0in && y1in) ? t10 : 0.0f;
    r.w = (zin && x1in && y1in) ? t11 : 0.0f;
    return r;
}

__global__ void __launch_bounds__(128) sample_kernel(float* __restrict__ out) {
    int w = threadIdx.x >> 5;
    int t = threadIdx.x & 31;
    int row = blockIdx.x * 4 + w;
    int aa = row / OUTN, bb = row % OUTN;

    __shared__ float Gx[4][64], Gy[4][64], Gz[4][64];
    __shared__ float Obuf[4][192];

    const float scale = 63.0f / 191.0f;
    float pa = (float)aa * scale; int i0 = min((int)pa, 62); float wi = pa - (float)i0;
    float pb = (float)bb * scale; int j0 = min((int)pb, 62); float wj = pb - (float)j0;
    float u = 1.0f - wi, v = 1.0f - wj;
    int base = (i0 << 12) + (j0 << 6);

#pragma unroll
    for (int sb = 0; sb < 2; sb++) {
        int s = t + sb * 32;
        {
            float a00 = gMX[base + s],      a10 = gMX[base + 4096 + s];
            float a01 = gMX[base + 64 + s], a11 = gMX[base + 4160 + s];
            Gx[w][s] = (a00 * u + a10 * wi) * v + (a01 * u + a11 * wi) * wj;
        }
        {
            float a00 = gMY[base + s],      a10 = gMY[base + 4096 + s];
            float a01 = gMY[base + 64 + s], a11 = gMY[base + 4160 + s];
            Gy[w][s] = (a00 * u + a10 * wi) * v + (a01 * u + a11 * wi) * wj;
        }
        {
            float a00 = gMZ[base + s],      a10 = gMZ[base + 4096 + s];
            float a01 = gMZ[base + 64 + s], a11 = gMZ[base + 4160 + s];
            Gz[w][s] = (a00 * u + a10 * wi) * v + (a01 * u + a11 * wi) * wj;
        }
    }
    __syncwarp();

    int px = 0x7fffffff, py = 0x7fffffff, pz = 0x7fffffff;
    float4 pl0 = make_float4(0.f, 0.f, 0.f, 0.f), pl1 = pl0;

#pragma unroll
    for (int q = 0; q < 6; q++) {
        int cc = t * 6 + q;
        float pc = (float)cc * scale; int s0 = min((int)pc, 62); float ws = pc - (float)s0;
        float gx = Gx[w][s0] * (1.0f - ws) + Gx[w][s0 + 1] * ws;
        float gy = Gy[w][s0] * (1.0f - ws) + Gy[w][s0 + 1] * ws;
        float gz = Gz[w][s0] * (1.0f - ws) + Gz[w][s0 + 1] * ws;

        float ix = (gx + 1.0f) * 0.5f * 191.0f;
        float iy = (gy + 1.0f) * 0.5f * 191.0f;
        float iz = (gz + 1.0f) * 0.5f * 191.0f;
        float xf = floorf(ix), yf = floorf(iy), zf = floorf(iz);
        float fx = ix - xf, fy = iy - yf, fz = iz - zf;
        int x0 = (int)xf, y0 = (int)yf, z0 = (int)zf;

        bool samexy = (x0 == px) && (y0 == py);
        if (samexy && z0 == pz + 1) {
            pl0 = pl1;
            pl1 = load_plane(x0, y0, z0 + 1);
        } else if (!(samexy && z0 == pz)) {
            pl0 = load_plane(x0, y0, z0);
            pl1 = load_plane(x0, y0, z0 + 1);
        }
        px = x0; py = y0; pz = z0;

        float ux = 1.0f - fx, uy = 1.0f - fy;
        float r0 = uy * (ux * pl0.x + fx * pl0.y) + fy * (ux * pl0.z + fx * pl0.w);
        float r1 = uy * (ux * pl1.x + fx * pl1.y) + fy * (ux * pl1.z + fx * pl1.w);
        Obuf[w][cc] = r0 * (1.0f - fz) + r1 * fz;
    }
    __syncwarp();

    int obase = row * OUTN;
#pragma unroll
    for (int s = 0; s < 6; s++) out[obase + s * 32 + t] = Obuf[w][s * 32 + t];
}

// ---------------- launch ----------------
extern "C" void kernel_launch(void* const* d_in, const int* in_sizes, int n_in,
                              void* d_out, int out_size) {
    const float* phantom = nullptr;
    const float* RI      = nullptr;
    const float* ray0    = nullptr;
    for (int i = 0; i < n_in; i++) {
        if      (in_sizes[i] == OUT3)                phantom = (const float*)d_in[i];
        else if (in_sizes[i] == KGRID*KGRID*KGRID*2) RI      = (const float*)d_in[i];
        else if (in_sizes[i] == NRAY2 * 5)           ray0    = (const float*)d_in[i];
    }
    float* out = (float*)d_out;

    ray_build_kernel<<<RAY_BLOCKS + BUILD_BLOCKS, 128>>>(RI, ray0, phantom);
    sample_kernel<<<OUTN * OUTN / 4, 128>>>(out);
}